// round 1
// baseline (speedup 1.0000x reference)
#include <cuda_runtime.h>

#define BB 2
#define SS 2048
#define DD 1024
#define HH 16
#define HDD 64
#define NTOK (BB*SS)   // 4096

// Scratch (allocation-free rule: __device__ globals)
__device__ float g_q[NTOK*DD];
__device__ float g_k[NTOK*DD];
__device__ float g_v[NTOK*DD];
__device__ float g_ctx[NTOK*DD];

// ---------------------------------------------------------------------------
// SGEMM-NT: C[M,N] = A[M,K] * W[N,K]^T   (both row-major, K contiguous)
// BM=BN=128, BK=8, 256 threads, 8x8 per-thread micro-tile.
// M,N,K all multiples of 128/8 here -> no bounds checks.
// ---------------------------------------------------------------------------
__global__ __launch_bounds__(256) void sgemm_nt(
    const float* __restrict__ A, const float* __restrict__ W,
    float* __restrict__ C, int M, int N, int K)
{
    __shared__ float As[8][128];
    __shared__ float Bs[8][128];

    const int tid = threadIdx.x;
    const int bm = blockIdx.y * 128;
    const int bn = blockIdx.x * 128;

    const int lrow = tid >> 1;          // 0..127
    const int lcol = (tid & 1) * 4;     // 0 or 4

    const float* Ap = A + (size_t)(bm + lrow) * K + lcol;
    const float* Wp = W + (size_t)(bn + lrow) * K + lcol;

    const int ty = tid >> 4;            // 0..15
    const int tx = tid & 15;            // 0..15

    float acc[8][8];
    #pragma unroll
    for (int i = 0; i < 8; i++)
        #pragma unroll
        for (int j = 0; j < 8; j++) acc[i][j] = 0.f;

    for (int k0 = 0; k0 < K; k0 += 8) {
        float4 a = *(const float4*)(Ap + k0);
        float4 b = *(const float4*)(Wp + k0);
        As[lcol + 0][lrow] = a.x; As[lcol + 1][lrow] = a.y;
        As[lcol + 2][lrow] = a.z; As[lcol + 3][lrow] = a.w;
        Bs[lcol + 0][lrow] = b.x; Bs[lcol + 1][lrow] = b.y;
        Bs[lcol + 2][lrow] = b.z; Bs[lcol + 3][lrow] = b.w;
        __syncthreads();

        #pragma unroll
        for (int kk = 0; kk < 8; kk++) {
            float4 a0 = *(const float4*)&As[kk][ty * 8];
            float4 a1 = *(const float4*)&As[kk][ty * 8 + 4];
            float4 b0 = *(const float4*)&Bs[kk][tx * 8];
            float4 b1 = *(const float4*)&Bs[kk][tx * 8 + 4];
            float ar[8] = {a0.x, a0.y, a0.z, a0.w, a1.x, a1.y, a1.z, a1.w};
            float br[8] = {b0.x, b0.y, b0.z, b0.w, b1.x, b1.y, b1.z, b1.w};
            #pragma unroll
            for (int i = 0; i < 8; i++)
                #pragma unroll
                for (int j = 0; j < 8; j++)
                    acc[i][j] += ar[i] * br[j];
        }
        __syncthreads();
    }

    #pragma unroll
    for (int i = 0; i < 8; i++) {
        float* cp = C + (size_t)(bm + ty * 8 + i) * N + bn + tx * 8;
        float4 c0 = {acc[i][0], acc[i][1], acc[i][2], acc[i][3]};
        float4 c1 = {acc[i][4], acc[i][5], acc[i][6], acc[i][7]};
        *(float4*)(cp)     = c0;
        *(float4*)(cp + 4) = c1;
    }
}

// ---------------------------------------------------------------------------
// Flash attention with causal mask + ALiBi.
// Q/K/V layout: [token, D] with head h occupying cols [h*64, h*64+64).
// Grid: x = S/128 q-tiles, y = B*H. 128 threads, 1 thread = 1 q row.
// scores = (q.k)/8 + slope*(q_idx - k_idx), slope = 2^(-0.5*(h+1))
// ---------------------------------------------------------------------------
__global__ __launch_bounds__(128) void attn_kernel(
    const float* __restrict__ Q, const float* __restrict__ K,
    const float* __restrict__ V, float* __restrict__ O)
{
    __shared__ float ks[64][64];
    __shared__ float vs[64][64];

    const int bh = blockIdx.y;
    const int b  = bh >> 4;
    const int h  = bh & 15;
    const int q_idx = blockIdx.x * 128 + threadIdx.x;   // seq position

    const float slope = exp2f(-0.5f * (float)(h + 1));
    const float scale = 0.125f;   // 1/sqrt(64)

    float qreg[64];
    {
        const float4* qp = (const float4*)(Q + ((size_t)(b * SS + q_idx)) * DD + h * HDD);
        #pragma unroll
        for (int i = 0; i < 16; i++) {
            float4 t = qp[i];
            qreg[4 * i + 0] = t.x * scale;
            qreg[4 * i + 1] = t.y * scale;
            qreg[4 * i + 2] = t.z * scale;
            qreg[4 * i + 3] = t.w * scale;
        }
    }

    float acc[64];
    #pragma unroll
    for (int i = 0; i < 64; i++) acc[i] = 0.f;
    float mmax = -1e30f;
    float lsum = 0.f;

    const int ktiles = blockIdx.x * 2 + 2;   // cover k in [0, blk_q_end]

    for (int kt = 0; kt < ktiles; kt++) {
        // cooperative load: 64 rows x 64 floats for K and V
        {
            const int r = threadIdx.x >> 1;            // 0..63
            const int c = (threadIdx.x & 1) * 32;      // 0 or 32
            const float4* kp = (const float4*)(K + ((size_t)(b * SS + kt * 64 + r)) * DD + h * HDD + c);
            const float4* vp = (const float4*)(V + ((size_t)(b * SS + kt * 64 + r)) * DD + h * HDD + c);
            float4* kd = (float4*)&ks[r][c];
            float4* vd = (float4*)&vs[r][c];
            #pragma unroll
            for (int i = 0; i < 8; i++) { kd[i] = kp[i]; }
            #pragma unroll
            for (int i = 0; i < 8; i++) { vd[i] = vp[i]; }
        }
        __syncthreads();

        const int base = kt * 64;
        #pragma unroll 4
        for (int j = 0; j < 64; j++) {
            const int kk = base + j;
            if (kk <= q_idx) {
                const float4* kr = (const float4*)&ks[j][0];
                float s0 = 0.f, s1 = 0.f, s2 = 0.f, s3 = 0.f;
                #pragma unroll
                for (int i = 0; i < 16; i++) {
                    float4 kv = kr[i];
                    s0 += qreg[4 * i + 0] * kv.x;
                    s1 += qreg[4 * i + 1] * kv.y;
                    s2 += qreg[4 * i + 2] * kv.z;
                    s3 += qreg[4 * i + 3] * kv.w;
                }
                float s = (s0 + s1) + (s2 + s3) + slope * (float)(q_idx - kk);

                if (s > mmax) {
                    float corr = __expf(mmax - s);
                    lsum *= corr;
                    #pragma unroll
                    for (int d = 0; d < 64; d++) acc[d] *= corr;
                    mmax = s;
                }
                float p = __expf(s - mmax);
                lsum += p;
                const float4* vr = (const float4*)&vs[j][0];
                #pragma unroll
                for (int i = 0; i < 16; i++) {
                    float4 vv = vr[i];
                    acc[4 * i + 0] += p * vv.x;
                    acc[4 * i + 1] += p * vv.y;
                    acc[4 * i + 2] += p * vv.z;
                    acc[4 * i + 3] += p * vv.w;
                }
            }
        }
        __syncthreads();
    }

    const float inv = 1.f / lsum;
    float* op = O + ((size_t)(b * SS + q_idx)) * DD + h * HDD;
    #pragma unroll
    for (int i = 0; i < 16; i++) {
        float4 o;
        o.x = acc[4 * i + 0] * inv;
        o.y = acc[4 * i + 1] * inv;
        o.z = acc[4 * i + 2] * inv;
        o.w = acc[4 * i + 3] * inv;
        *(float4*)(op + 4 * i) = o;
    }
}

extern "C" void kernel_launch(void* const* d_in, const int* in_sizes, int n_in,
                              void* d_out, int out_size)
{
    (void)in_sizes; (void)n_in; (void)out_size;
    const float* x  = (const float*)d_in[0];
    const float* Wq = (const float*)d_in[1];
    const float* Wk = (const float*)d_in[2];
    const float* Wv = (const float*)d_in[3];
    const float* Wo = (const float*)d_in[4];
    float* out = (float*)d_out;

    float *qp, *kp, *vp, *cp;
    cudaGetSymbolAddress((void**)&qp, g_q);
    cudaGetSymbolAddress((void**)&kp, g_k);
    cudaGetSymbolAddress((void**)&vp, g_v);
    cudaGetSymbolAddress((void**)&cp, g_ctx);

    dim3 gemm_grid(DD / 128, NTOK / 128);   // (8, 32)
    sgemm_nt<<<gemm_grid, 256>>>(x, Wq, qp, NTOK, DD, DD);
    sgemm_nt<<<gemm_grid, 256>>>(x, Wk, kp, NTOK, DD, DD);
    sgemm_nt<<<gemm_grid, 256>>>(x, Wv, vp, NTOK, DD, DD);

    dim3 attn_grid(SS / 128, BB * HH);      // (16, 32)
    attn_kernel<<<attn_grid, 128>>>(qp, kp, vp, cp);

    sgemm_nt<<<gemm_grid, 256>>>(cp, Wo, out, NTOK, DD, DD);
}

// round 4
// speedup vs baseline: 3.8866x; 3.8866x over previous
#include <cuda_runtime.h>
#include <cuda_bf16.h>
#include <cstdint>

#define BB 2
#define SS 2048
#define DD 1024
#define HH 16
#define NTOK 4096
#define GK3 3072   // 3-plane split K: A=[hi|lo|hi], B=[hi|hi|lo]

// ---------------- device-global scratch (allocation-free rule) -------------
__device__ __nv_bfloat16 g_xc[(size_t)NTOK * GK3];   // x split        [4096,3072]
__device__ __nv_bfloat16 g_wc[(size_t)3072 * GK3];   // Wq|Wk|Wv split [3072,3072]
__device__ __nv_bfloat16 g_woc[(size_t)DD * GK3];    // Wo split       [1024,3072]
__device__ __nv_bfloat16 g_qh[(size_t)NTOK * DD];    // q hi (pre-scaled 1/8)
__device__ __nv_bfloat16 g_ql[(size_t)NTOK * DD];
__device__ __nv_bfloat16 g_kh[(size_t)NTOK * DD];
__device__ __nv_bfloat16 g_kl[(size_t)NTOK * DD];
__device__ __nv_bfloat16 g_vh[(size_t)NTOK * DD];
__device__ __nv_bfloat16 g_vl[(size_t)NTOK * DD];
__device__ __nv_bfloat16 g_ctxc[(size_t)NTOK * GK3]; // attn out split [4096,3072]

// ---------------- PTX helpers (base ISA, compute_103-safe) -----------------
__device__ __forceinline__ uint32_t smem_u32(const void* p) {
    return (uint32_t)__cvta_generic_to_shared(p);
}
__device__ __forceinline__ void cp16(uint32_t dst, const void* src) {
    asm volatile("cp.async.cg.shared.global [%0], [%1], 16;" :: "r"(dst), "l"(src));
}
__device__ __forceinline__ void cp_commit() {
    asm volatile("cp.async.commit_group;" ::: "memory");
}
template <int N> __device__ __forceinline__ void cp_wait() {
    asm volatile("cp.async.wait_group %0;" :: "n"(N) : "memory");
}
__device__ __forceinline__ void ldsm4(uint32_t* r, uint32_t a) {
    asm volatile("ldmatrix.sync.aligned.m8n8.x4.shared.b16 {%0,%1,%2,%3}, [%4];"
                 : "=r"(r[0]), "=r"(r[1]), "=r"(r[2]), "=r"(r[3]) : "r"(a));
}
__device__ __forceinline__ void ldsm4t(uint32_t* r, uint32_t a) {
    asm volatile("ldmatrix.sync.aligned.m8n8.x4.trans.shared.b16 {%0,%1,%2,%3}, [%4];"
                 : "=r"(r[0]), "=r"(r[1]), "=r"(r[2]), "=r"(r[3]) : "r"(a));
}
__device__ __forceinline__ void mma16816(float* d, const uint32_t* a,
                                         uint32_t b0, uint32_t b1) {
    asm volatile(
        "mma.sync.aligned.m16n8k16.row.col.f32.bf16.bf16.f32 "
        "{%0,%1,%2,%3},{%4,%5,%6,%7},{%8,%9},{%0,%1,%2,%3};"
        : "+f"(d[0]), "+f"(d[1]), "+f"(d[2]), "+f"(d[3])
        : "r"(a[0]), "r"(a[1]), "r"(a[2]), "r"(a[3]), "r"(b0), "r"(b1));
}
// pack two fp32 -> bf16x2 hi reg, residual lo reg
__device__ __forceinline__ uint32_t pack_hilo(float a, float b, uint32_t& lo) {
    __nv_bfloat162 h = __floats2bfloat162_rn(a, b);
    __nv_bfloat162 l = __floats2bfloat162_rn(a - __bfloat162float(h.x),
                                             b - __bfloat162float(h.y));
    lo = *reinterpret_cast<uint32_t*>(&l);
    return *reinterpret_cast<uint32_t*>(&h);
}
// write [hi | lo | hi] pair into a 3072-wide split row at column c
__device__ __forceinline__ void write_split3(__nv_bfloat16* row, int c,
                                             float a, float b) {
    __nv_bfloat162 h = __floats2bfloat162_rn(a, b);
    __nv_bfloat162 l = __floats2bfloat162_rn(a - __bfloat162float(h.x),
                                             b - __bfloat162float(h.y));
    *(__nv_bfloat162*)(row + c) = h;
    *(__nv_bfloat162*)(row + 1024 + c) = l;
    *(__nv_bfloat162*)(row + 2048 + c) = h;
}

// ---------------------------------------------------------------------------
// split3: fp32 [rows,1024] -> bf16 [rows,3072]
// mode 0 (A operand): [hi | lo | hi];  mode 1 (B operand): [hi | hi | lo]
// ---------------------------------------------------------------------------
__global__ __launch_bounds__(256) void split3(
    const float* __restrict__ src, __nv_bfloat16* __restrict__ dst,
    int mode, int total)
{
    int idx = blockIdx.x * blockDim.x + threadIdx.x;
    if (idx >= total) return;
    int r = idx >> 10;
    int c = idx & 1023;
    float v = src[idx];
    __nv_bfloat16 h = __float2bfloat16(v);
    __nv_bfloat16 l = __float2bfloat16(v - __bfloat162float(h));
    size_t base = (size_t)r * GK3;
    if (mode == 0) {
        dst[base + c] = h; dst[base + 1024 + c] = l; dst[base + 2048 + c] = h;
    } else {
        dst[base + c] = h; dst[base + 1024 + c] = h; dst[base + 2048 + c] = l;
    }
}

// ---------------------------------------------------------------------------
// bf16 mma GEMM-NT: C[M,N] = A[M,3072] * B[N,3072]^T, fp32 accum.
// 128x128 tile, 256 threads (8 warps 2x4), K-chunk 64, cp.async double buffer.
// mode 0: fp32 C (ldc). mode 1: fused QKV epilogue -> bf16 hi/lo planes.
// ---------------------------------------------------------------------------
#define GKCH 64
#define GNCH (GK3 / GKCH)   // 48
#define GTILE 16384          // 128 rows x 128 bytes

__device__ __forceinline__ void g_load(const __nv_bfloat16* __restrict__ A,
                                       const __nv_bfloat16* __restrict__ B,
                                       uint32_t sA, uint32_t sB,
                                       int m0, int n0, int kt, int tid)
{
    const int ra = tid >> 1;
    const int cb = (tid & 1) * 64;
    const char* ga = (const char*)(A + (size_t)(m0 + ra) * GK3 + kt * GKCH) + cb;
    const char* gb = (const char*)(B + (size_t)(n0 + ra) * GK3 + kt * GKCH) + cb;
    const uint32_t swr = (uint32_t)((ra & 7) << 4);
    #pragma unroll
    for (int i = 0; i < 4; i++) {
        uint32_t off = (uint32_t)(cb + i * 16) ^ swr;
        cp16(sA + ra * 128 + off, ga + i * 16);
        cp16(sB + ra * 128 + off, gb + i * 16);
    }
    cp_commit();
}

__global__ __launch_bounds__(256) void gemm_mma(
    const __nv_bfloat16* __restrict__ A, const __nv_bfloat16* __restrict__ B,
    float* __restrict__ C, int ldc, int mode)
{
    extern __shared__ char smem[];
    const uint32_t sb = smem_u32(smem);
    const uint32_t sA[2] = { sb,         sb + 2 * GTILE };
    const uint32_t sB[2] = { sb + GTILE, sb + 3 * GTILE };

    const int tid = threadIdx.x;
    const int lane = tid & 31;
    const int wid = tid >> 5;
    const int wm = wid >> 2;
    const int wn = wid & 3;
    const int m0 = blockIdx.y * 128;
    const int n0 = blockIdx.x * 128;

    const int srow = (lane & 7) + ((lane >> 3) & 1) * 8;
    const uint32_t swz_row = (uint32_t)((lane & 7) << 4);
    const int g  = lane >> 2;
    const int tg = lane & 3;

    float acc[4][4][4];
    #pragma unroll
    for (int i = 0; i < 4; i++)
        #pragma unroll
        for (int j = 0; j < 4; j++)
            #pragma unroll
            for (int k = 0; k < 4; k++) acc[i][j][k] = 0.f;

    g_load(A, B, sA[0], sB[0], m0, n0, 0, tid);
    g_load(A, B, sA[1], sB[1], m0, n0, 1, tid);

    #pragma unroll 1
    for (int kt = 0; kt < GNCH; kt++) {
        const int s = kt & 1;
        if (kt < GNCH - 1) cp_wait<1>(); else cp_wait<0>();
        __syncthreads();

        #pragma unroll
        for (int ks = 0; ks < 4; ks++) {
            const uint32_t swz = (uint32_t)(ks * 32 + ((lane >> 4) << 4)) ^ swz_row;
            uint32_t bfr[2][4];
            #pragma unroll
            for (int p = 0; p < 2; p++)
                ldsm4(bfr[p], sB[s] + (wn * 32 + p * 16 + srow) * 128 + swz);
            #pragma unroll
            for (int mt = 0; mt < 4; mt++) {
                uint32_t af[4];
                ldsm4(af, sA[s] + (wm * 64 + mt * 16 + srow) * 128 + swz);
                mma16816(acc[mt][0], af, bfr[0][0], bfr[0][2]);
                mma16816(acc[mt][1], af, bfr[0][1], bfr[0][3]);
                mma16816(acc[mt][2], af, bfr[1][0], bfr[1][2]);
                mma16816(acc[mt][3], af, bfr[1][1], bfr[1][3]);
            }
        }
        __syncthreads();
        if (kt + 2 < GNCH)
            g_load(A, B, sA[s], sB[s], m0, n0, kt + 2, tid);
    }

    if (mode == 0) {
        #pragma unroll
        for (int mt = 0; mt < 4; mt++) {
            const int r0 = m0 + wm * 64 + mt * 16 + g;
            #pragma unroll
            for (int nt = 0; nt < 4; nt++) {
                const int col = n0 + wn * 32 + nt * 8 + tg * 2;
                float2 v0 = { acc[mt][nt][0], acc[mt][nt][1] };
                float2 v1 = { acc[mt][nt][2], acc[mt][nt][3] };
                *(float2*)(C + (size_t)r0 * ldc + col) = v0;
                *(float2*)(C + (size_t)(r0 + 8) * ldc + col) = v1;
            }
        }
    } else {
        const int sect = n0 >> 10;   // 0=q, 1=k, 2=v (constant per CTA)
        __nv_bfloat16* bh = (sect == 0) ? g_qh : (sect == 1) ? g_kh : g_vh;
        __nv_bfloat16* bl = (sect == 0) ? g_ql : (sect == 1) ? g_kl : g_vl;
        const float scl = (sect == 0) ? 0.125f : 1.0f;
        #pragma unroll
        for (int mt = 0; mt < 4; mt++) {
            const int r0 = m0 + wm * 64 + mt * 16 + g;
            #pragma unroll
            for (int nt = 0; nt < 4; nt++) {
                const int col = (n0 + wn * 32 + nt * 8 + tg * 2) & 1023;
                uint32_t lo0, lo1;
                uint32_t h0 = pack_hilo(acc[mt][nt][0] * scl, acc[mt][nt][1] * scl, lo0);
                uint32_t h1 = pack_hilo(acc[mt][nt][2] * scl, acc[mt][nt][3] * scl, lo1);
                *(uint32_t*)(bh + (size_t)r0 * DD + col) = h0;
                *(uint32_t*)(bl + (size_t)r0 * DD + col) = lo0;
                *(uint32_t*)(bh + (size_t)(r0 + 8) * DD + col) = h1;
                *(uint32_t*)(bl + (size_t)(r0 + 8) * DD + col) = lo1;
            }
        }
    }
}

// ---------------------------------------------------------------------------
// Flash attention, mma.sync. 4 warps, 64 q rows/block, 64-row KV tiles.
// smem planes (8KB): 0=qh 1=ql 2=kh 3=kl 4=vh 5=vl
// scores = qh.kh + ql.kh + qh.kl ; PV = ph.vh + pl.vh + ph.vl
// bias +slope*(q-k), causal mask, online softmax on fragments.
// Output written as 3-plane bf16 split directly to g_ctxc.
// ---------------------------------------------------------------------------
__global__ __launch_bounds__(128) void attn_mma()
{
    extern __shared__ char smem[];
    const uint32_t sb = smem_u32(smem);

    const int tid = threadIdx.x;
    const int lane = tid & 31;
    const int w = tid >> 5;
    const int qt = blockIdx.x;
    const int bh = blockIdx.y;
    const int b = bh >> 4;
    const int h = bh & 15;
    const int qbase = qt * 64;

    const float slope = exp2f(-0.5f * (float)(h + 1));
    const int g  = lane >> 2;
    const int tg = lane & 3;
    const int srow = (lane & 7) + ((lane >> 3) & 1) * 8;
    const uint32_t swz_row = (uint32_t)((lane & 7) << 4);

    const int qr0 = qbase + w * 16 + g;
    const int qr1 = qr0 + 8;
    const float fq0 = (float)qr0;
    const float fq1 = (float)qr1;

    // ---- load q planes (qh already scaled by 1/8)
    {
        const int p = tid >> 6;        // 0..1
        const int r = tid & 63;
        const __nv_bfloat16* src =
            (p ? g_ql : g_qh) + (size_t)(b * SS + qbase + r) * DD + h * 64;
        const uint32_t d = sb + p * 8192 + r * 128;
        const uint32_t swr = (uint32_t)((r & 7) << 4);
        #pragma unroll
        for (int i = 0; i < 8; i++)
            cp16(d + ((uint32_t)(i * 16) ^ swr), src + i * 8);
    }
    cp_commit(); cp_wait<0>();
    __syncthreads();

    // q fragments in registers (2 planes x 4 ksteps x 4 regs)
    uint32_t qf[2][4][4];
    #pragma unroll
    for (int p = 0; p < 2; p++)
        #pragma unroll
        for (int kk = 0; kk < 4; kk++)
            ldsm4(qf[p][kk], sb + p * 8192 + (w * 16 + srow) * 128 +
                  ((uint32_t)(kk * 32 + ((lane >> 4) << 4)) ^ swz_row));

    float acc[8][4];
    #pragma unroll
    for (int i = 0; i < 8; i++)
        #pragma unroll
        for (int j = 0; j < 4; j++) acc[i][j] = 0.f;
    float rm0 = -1e30f, rm1 = -1e30f, l0 = 0.f, l1 = 0.f;

    for (int kt = 0; kt <= qt; kt++) {
        __syncthreads();   // previous tile fully consumed before overwrite
        // ---- warp w loads plane 2+w (kh,kl,vh,vl), 64 rows x 128B
        {
            const __nv_bfloat16* gp = (w == 0) ? g_kh : (w == 1) ? g_kl
                                     : (w == 2) ? g_vh : g_vl;
            const uint32_t base = sb + (2 + w) * 8192;
            #pragma unroll
            for (int half = 0; half < 2; half++) {
                const int r = lane + half * 32;
                const __nv_bfloat16* src =
                    gp + (size_t)(b * SS + kt * 64 + r) * DD + h * 64;
                const uint32_t swr = (uint32_t)((r & 7) << 4);
                #pragma unroll
                for (int i = 0; i < 8; i++)
                    cp16(base + r * 128 + ((uint32_t)(i * 16) ^ swr), src + i * 8);
            }
        }
        cp_commit(); cp_wait<0>();
        __syncthreads();

        // ---- scores
        float S[8][4];
        #pragma unroll
        for (int i = 0; i < 8; i++)
            #pragma unroll
            for (int j = 0; j < 4; j++) S[i][j] = 0.f;

        #pragma unroll
        for (int kk = 0; kk < 4; kk++) {      // kh plane: qh & ql
            const uint32_t swz = (uint32_t)(kk * 32 + ((lane >> 4) << 4)) ^ swz_row;
            #pragma unroll
            for (int j = 0; j < 4; j++) {
                uint32_t bf[4];
                ldsm4(bf, sb + 2 * 8192 + (j * 16 + srow) * 128 + swz);
                mma16816(S[2 * j],     qf[0][kk], bf[0], bf[2]);
                mma16816(S[2 * j + 1], qf[0][kk], bf[1], bf[3]);
                mma16816(S[2 * j],     qf[1][kk], bf[0], bf[2]);
                mma16816(S[2 * j + 1], qf[1][kk], bf[1], bf[3]);
            }
        }
        #pragma unroll
        for (int kk = 0; kk < 4; kk++) {      // kl plane: qh only
            const uint32_t swz = (uint32_t)(kk * 32 + ((lane >> 4) << 4)) ^ swz_row;
            #pragma unroll
            for (int j = 0; j < 4; j++) {
                uint32_t bf[4];
                ldsm4(bf, sb + 3 * 8192 + (j * 16 + srow) * 128 + swz);
                mma16816(S[2 * j],     qf[0][kk], bf[0], bf[2]);
                mma16816(S[2 * j + 1], qf[0][kk], bf[1], bf[3]);
            }
        }

        // ---- bias + causal mask + online softmax
        const float kb = (float)(kt * 64);
        float tm0 = -1e30f, tm1 = -1e30f;
        #pragma unroll
        for (int nt = 0; nt < 8; nt++) {
            const float c0 = kb + (float)(nt * 8 + tg * 2);
            const float c1 = c0 + 1.f;
            float s00 = S[nt][0] + slope * (fq0 - c0);
            float s01 = S[nt][1] + slope * (fq0 - c1);
            float s10 = S[nt][2] + slope * (fq1 - c0);
            float s11 = S[nt][3] + slope * (fq1 - c1);
            s00 = (c0 <= fq0) ? s00 : -1e30f;
            s01 = (c1 <= fq0) ? s01 : -1e30f;
            s10 = (c0 <= fq1) ? s10 : -1e30f;
            s11 = (c1 <= fq1) ? s11 : -1e30f;
            S[nt][0] = s00; S[nt][1] = s01; S[nt][2] = s10; S[nt][3] = s11;
            tm0 = fmaxf(tm0, fmaxf(s00, s01));
            tm1 = fmaxf(tm1, fmaxf(s10, s11));
        }
        tm0 = fmaxf(tm0, __shfl_xor_sync(0xffffffffu, tm0, 1));
        tm0 = fmaxf(tm0, __shfl_xor_sync(0xffffffffu, tm0, 2));
        tm1 = fmaxf(tm1, __shfl_xor_sync(0xffffffffu, tm1, 1));
        tm1 = fmaxf(tm1, __shfl_xor_sync(0xffffffffu, tm1, 2));

        const float nm0 = fmaxf(rm0, tm0);
        const float nm1 = fmaxf(rm1, tm1);
        const float corr0 = __expf(rm0 - nm0);
        const float corr1 = __expf(rm1 - nm1);
        rm0 = nm0; rm1 = nm1;

        float ts0 = 0.f, ts1 = 0.f;
        #pragma unroll
        for (int nt = 0; nt < 8; nt++) {
            S[nt][0] = __expf(S[nt][0] - rm0);
            S[nt][1] = __expf(S[nt][1] - rm0);
            S[nt][2] = __expf(S[nt][2] - rm1);
            S[nt][3] = __expf(S[nt][3] - rm1);
            ts0 += S[nt][0] + S[nt][1];
            ts1 += S[nt][2] + S[nt][3];
        }
        ts0 += __shfl_xor_sync(0xffffffffu, ts0, 1);
        ts0 += __shfl_xor_sync(0xffffffffu, ts0, 2);
        ts1 += __shfl_xor_sync(0xffffffffu, ts1, 1);
        ts1 += __shfl_xor_sync(0xffffffffu, ts1, 2);
        l0 = l0 * corr0 + ts0;
        l1 = l1 * corr1 + ts1;

        #pragma unroll
        for (int nt = 0; nt < 8; nt++) {
            acc[nt][0] *= corr0; acc[nt][1] *= corr0;
            acc[nt][2] *= corr1; acc[nt][3] *= corr1;
        }

        // ---- PV: P a-frags from registers, V via ldmatrix.trans
        uint32_t ahs[4][4];
        #pragma unroll
        for (int kk = 0; kk < 4; kk++) {
            uint32_t al[4];
            ahs[kk][0] = pack_hilo(S[2 * kk][0],     S[2 * kk][1],     al[0]);
            ahs[kk][1] = pack_hilo(S[2 * kk][2],     S[2 * kk][3],     al[1]);
            ahs[kk][2] = pack_hilo(S[2 * kk + 1][0], S[2 * kk + 1][1], al[2]);
            ahs[kk][3] = pack_hilo(S[2 * kk + 1][2], S[2 * kk + 1][3], al[3]);
            const int vr = kk * 16 + ((lane >> 4) & 1) * 8 + (lane & 7);
            const uint32_t vb = (uint32_t)((((lane >> 3) & 1)) << 4);
            #pragma unroll
            for (int j = 0; j < 4; j++) {
                uint32_t vf[4];
                ldsm4t(vf, sb + 4 * 8192 + vr * 128 +
                       (((uint32_t)(j * 32) + vb) ^ ((uint32_t)(vr & 7) << 4)));
                mma16816(acc[2 * j],     ahs[kk], vf[0], vf[2]);
                mma16816(acc[2 * j + 1], ahs[kk], vf[1], vf[3]);
                mma16816(acc[2 * j],     al,      vf[0], vf[2]);
                mma16816(acc[2 * j + 1], al,      vf[1], vf[3]);
            }
        }
        #pragma unroll
        for (int kk = 0; kk < 4; kk++) {      // vl plane: ph only
            const int vr = kk * 16 + ((lane >> 4) & 1) * 8 + (lane & 7);
            const uint32_t vb = (uint32_t)((((lane >> 3) & 1)) << 4);
            #pragma unroll
            for (int j = 0; j < 4; j++) {
                uint32_t vf[4];
                ldsm4t(vf, sb + 5 * 8192 + vr * 128 +
                       (((uint32_t)(j * 32) + vb) ^ ((uint32_t)(vr & 7) << 4)));
                mma16816(acc[2 * j],     ahs[kk], vf[0], vf[2]);
                mma16816(acc[2 * j + 1], ahs[kk], vf[1], vf[3]);
            }
        }
    }

    // ---- epilogue: normalize, write 3-plane bf16 split ctx rows
    const float inv0 = 1.f / l0;
    const float inv1 = 1.f / l1;
    __nv_bfloat16* row0 = g_ctxc + (size_t)(b * SS + qr0) * GK3;
    __nv_bfloat16* row1 = g_ctxc + (size_t)(b * SS + qr1) * GK3;
    #pragma unroll
    for (int nt = 0; nt < 8; nt++) {
        const int c = h * 64 + nt * 8 + tg * 2;
        write_split3(row0, c, acc[nt][0] * inv0, acc[nt][1] * inv0);
        write_split3(row1, c, acc[nt][2] * inv1, acc[nt][3] * inv1);
    }
}

// ---------------------------------------------------------------------------
extern "C" void kernel_launch(void* const* d_in, const int* in_sizes, int n_in,
                              void* d_out, int out_size)
{
    (void)in_sizes; (void)n_in; (void)out_size;
    const float* x  = (const float*)d_in[0];
    const float* Wq = (const float*)d_in[1];
    const float* Wk = (const float*)d_in[2];
    const float* Wv = (const float*)d_in[3];
    const float* Wo = (const float*)d_in[4];
    float* out = (float*)d_out;

    __nv_bfloat16 *xc, *wc, *woc, *ctxc;
    cudaGetSymbolAddress((void**)&xc, g_xc);
    cudaGetSymbolAddress((void**)&wc, g_wc);
    cudaGetSymbolAddress((void**)&woc, g_woc);
    cudaGetSymbolAddress((void**)&ctxc, g_ctxc);

    const int SMEM_GEMM = 4 * GTILE;      // 65536
    const int SMEM_ATTN = 6 * 8192;       // 49152
    static bool attr_set = false;
    if (!attr_set) {
        cudaFuncSetAttribute(gemm_mma, cudaFuncAttributeMaxDynamicSharedMemorySize, SMEM_GEMM);
        cudaFuncSetAttribute(attn_mma, cudaFuncAttributeMaxDynamicSharedMemorySize, SMEM_ATTN);
        attr_set = true;
    }

    // fp32 -> bf16 3-plane splits
    split3<<<(NTOK * DD + 255) / 256, 256>>>(x, xc, 0, NTOK * DD);
    split3<<<(DD * DD + 255) / 256, 256>>>(Wq, wc, 1, DD * DD);
    split3<<<(DD * DD + 255) / 256, 256>>>(Wk, wc + (size_t)DD * GK3, 1, DD * DD);
    split3<<<(DD * DD + 255) / 256, 256>>>(Wv, wc + (size_t)2 * DD * GK3, 1, DD * DD);
    split3<<<(DD * DD + 255) / 256, 256>>>(Wo, woc, 1, DD * DD);

    // fused QKV projection with hi/lo epilogue
    gemm_mma<<<dim3(3 * DD / 128, NTOK / 128), 256, SMEM_GEMM>>>(xc, wc, nullptr, 0, 1);

    // attention (writes g_ctxc split directly)
    attn_mma<<<dim3(SS / 64, BB * HH), 128, SMEM_ATTN>>>();

    // output projection
    gemm_mma<<<dim3(DD / 128, NTOK / 128), 256, SMEM_GEMM>>>(ctxc, woc, out, DD, 0);
}

// round 5
// speedup vs baseline: 4.0954x; 1.0537x over previous
#include <cuda_runtime.h>
#include <cuda_bf16.h>
#include <cstdint>

#define BB 2
#define SS 2048
#define DD 1024
#define HH 16
#define NTOK 4096
#define GK3 3072   // 3-plane split K: A=[hi|lo|hi], B=[hi|hi|lo]

// ---------------- device-global scratch (allocation-free rule) -------------
__device__ __nv_bfloat16 g_xc[(size_t)NTOK * GK3];   // x split        [4096,3072]
__device__ __nv_bfloat16 g_wc[(size_t)3072 * GK3];   // Wq|Wk|Wv split [3072,3072]
__device__ __nv_bfloat16 g_woc[(size_t)DD * GK3];    // Wo split       [1024,3072]
__device__ __nv_bfloat16 g_qh[(size_t)NTOK * DD];    // q hi (pre-scaled 1/8)
__device__ __nv_bfloat16 g_ql[(size_t)NTOK * DD];
__device__ __nv_bfloat16 g_kh[(size_t)NTOK * DD];
__device__ __nv_bfloat16 g_kl[(size_t)NTOK * DD];
__device__ __nv_bfloat16 g_vh[(size_t)NTOK * DD];
__device__ __nv_bfloat16 g_vl[(size_t)NTOK * DD];
__device__ __nv_bfloat16 g_ctxc[(size_t)NTOK * GK3]; // attn out split [4096,3072]

// ---------------- PTX helpers (base ISA, compute_103-safe) -----------------
__device__ __forceinline__ uint32_t smem_u32(const void* p) {
    return (uint32_t)__cvta_generic_to_shared(p);
}
__device__ __forceinline__ void cp16(uint32_t dst, const void* src) {
    asm volatile("cp.async.cg.shared.global [%0], [%1], 16;" :: "r"(dst), "l"(src));
}
__device__ __forceinline__ void cp_commit() {
    asm volatile("cp.async.commit_group;" ::: "memory");
}
template <int N> __device__ __forceinline__ void cp_wait() {
    asm volatile("cp.async.wait_group %0;" :: "n"(N) : "memory");
}
__device__ __forceinline__ void ldsm4(uint32_t* r, uint32_t a) {
    asm volatile("ldmatrix.sync.aligned.m8n8.x4.shared.b16 {%0,%1,%2,%3}, [%4];"
                 : "=r"(r[0]), "=r"(r[1]), "=r"(r[2]), "=r"(r[3]) : "r"(a));
}
__device__ __forceinline__ void ldsm4t(uint32_t* r, uint32_t a) {
    asm volatile("ldmatrix.sync.aligned.m8n8.x4.trans.shared.b16 {%0,%1,%2,%3}, [%4];"
                 : "=r"(r[0]), "=r"(r[1]), "=r"(r[2]), "=r"(r[3]) : "r"(a));
}
__device__ __forceinline__ void mma16816(float* d, const uint32_t* a,
                                         uint32_t b0, uint32_t b1) {
    asm volatile(
        "mma.sync.aligned.m16n8k16.row.col.f32.bf16.bf16.f32 "
        "{%0,%1,%2,%3},{%4,%5,%6,%7},{%8,%9},{%0,%1,%2,%3};"
        : "+f"(d[0]), "+f"(d[1]), "+f"(d[2]), "+f"(d[3])
        : "r"(a[0]), "r"(a[1]), "r"(a[2]), "r"(a[3]), "r"(b0), "r"(b1));
}
__device__ __forceinline__ uint32_t pack_hilo(float a, float b, uint32_t& lo) {
    __nv_bfloat162 h = __floats2bfloat162_rn(a, b);
    __nv_bfloat162 l = __floats2bfloat162_rn(a - __bfloat162float(h.x),
                                             b - __bfloat162float(h.y));
    lo = *reinterpret_cast<uint32_t*>(&l);
    return *reinterpret_cast<uint32_t*>(&h);
}
__device__ __forceinline__ void write_split3(__nv_bfloat16* row, int c,
                                             float a, float b) {
    __nv_bfloat162 h = __floats2bfloat162_rn(a, b);
    __nv_bfloat162 l = __floats2bfloat162_rn(a - __bfloat162float(h.x),
                                             b - __bfloat162float(h.y));
    *(__nv_bfloat162*)(row + c) = h;
    *(__nv_bfloat162*)(row + 1024 + c) = l;
    *(__nv_bfloat162*)(row + 2048 + c) = h;
}

// ---------------------------------------------------------------------------
// split3: fp32 [rows,1024] -> bf16 [rows,3072]
// mode 0 (A operand): [hi | lo | hi];  mode 1 (B operand): [hi | hi | lo]
// ---------------------------------------------------------------------------
__global__ __launch_bounds__(256) void split3(
    const float* __restrict__ src, __nv_bfloat16* __restrict__ dst,
    int mode, int total)
{
    int idx = blockIdx.x * blockDim.x + threadIdx.x;
    if (idx >= total) return;
    int r = idx >> 10;
    int c = idx & 1023;
    float v = src[idx];
    __nv_bfloat16 h = __float2bfloat16(v);
    __nv_bfloat16 l = __float2bfloat16(v - __bfloat162float(h));
    size_t base = (size_t)r * GK3;
    if (mode == 0) {
        dst[base + c] = h; dst[base + 1024 + c] = l; dst[base + 2048 + c] = h;
    } else {
        dst[base + c] = h; dst[base + 1024 + c] = h; dst[base + 2048 + c] = l;
    }
}

// fused split of all 4 weight matrices (mode 1 layout): blockIdx.y selects W
__global__ __launch_bounds__(256) void split3_weights(
    const float* __restrict__ Wq, const float* __restrict__ Wk,
    const float* __restrict__ Wv, const float* __restrict__ Wo)
{
    const int m = blockIdx.y;
    const float* src = (m == 0) ? Wq : (m == 1) ? Wk : (m == 2) ? Wv : Wo;
    __nv_bfloat16* dst = (m < 3) ? (g_wc + (size_t)m * DD * GK3) : g_woc;
    int idx = blockIdx.x * blockDim.x + threadIdx.x;
    int r = idx >> 10;
    int c = idx & 1023;
    float v = src[idx];
    __nv_bfloat16 h = __float2bfloat16(v);
    __nv_bfloat16 l = __float2bfloat16(v - __bfloat162float(h));
    size_t base = (size_t)r * GK3;
    dst[base + c] = h; dst[base + 1024 + c] = h; dst[base + 2048 + c] = l;
}

// ---------------------------------------------------------------------------
// bf16 mma GEMM-NT: C[M,N] = A[M,3072] * B[N,3072]^T, fp32 accum.
// 128x128 tile, 256 threads (8 warps 2x4), K-chunk 64, cp.async double buffer.
// mode 0: fp32 C (ldc). mode 1: fused QKV epilogue -> bf16 hi/lo planes.
// ---------------------------------------------------------------------------
#define GKCH 64
#define GNCH (GK3 / GKCH)   // 48
#define GTILE 16384          // 128 rows x 128 bytes

__device__ __forceinline__ void g_load(const __nv_bfloat16* __restrict__ A,
                                       const __nv_bfloat16* __restrict__ B,
                                       uint32_t sA, uint32_t sB,
                                       int m0, int n0, int kt, int tid)
{
    const int ra = tid >> 1;
    const int cb = (tid & 1) * 64;
    const char* ga = (const char*)(A + (size_t)(m0 + ra) * GK3 + kt * GKCH) + cb;
    const char* gb = (const char*)(B + (size_t)(n0 + ra) * GK3 + kt * GKCH) + cb;
    const uint32_t swr = (uint32_t)((ra & 7) << 4);
    #pragma unroll
    for (int i = 0; i < 4; i++) {
        uint32_t off = (uint32_t)(cb + i * 16) ^ swr;
        cp16(sA + ra * 128 + off, ga + i * 16);
        cp16(sB + ra * 128 + off, gb + i * 16);
    }
    cp_commit();
}

__global__ __launch_bounds__(256) void gemm_mma(
    const __nv_bfloat16* __restrict__ A, const __nv_bfloat16* __restrict__ B,
    float* __restrict__ C, int ldc, int mode)
{
    extern __shared__ char smem[];
    const uint32_t sb = smem_u32(smem);
    const uint32_t sA[2] = { sb,         sb + 2 * GTILE };
    const uint32_t sB[2] = { sb + GTILE, sb + 3 * GTILE };

    const int tid = threadIdx.x;
    const int lane = tid & 31;
    const int wid = tid >> 5;
    const int wm = wid >> 2;
    const int wn = wid & 3;
    const int m0 = blockIdx.y * 128;
    const int n0 = blockIdx.x * 128;

    const int srow = (lane & 7) + ((lane >> 3) & 1) * 8;
    const uint32_t swz_row = (uint32_t)((lane & 7) << 4);
    const int g  = lane >> 2;
    const int tg = lane & 3;

    float acc[4][4][4];
    #pragma unroll
    for (int i = 0; i < 4; i++)
        #pragma unroll
        for (int j = 0; j < 4; j++)
            #pragma unroll
            for (int k = 0; k < 4; k++) acc[i][j][k] = 0.f;

    g_load(A, B, sA[0], sB[0], m0, n0, 0, tid);
    g_load(A, B, sA[1], sB[1], m0, n0, 1, tid);

    #pragma unroll 1
    for (int kt = 0; kt < GNCH; kt++) {
        const int s = kt & 1;
        if (kt < GNCH - 1) cp_wait<1>(); else cp_wait<0>();
        __syncthreads();

        #pragma unroll
        for (int ks = 0; ks < 4; ks++) {
            const uint32_t swz = (uint32_t)(ks * 32 + ((lane >> 4) << 4)) ^ swz_row;
            uint32_t bfr[2][4];
            #pragma unroll
            for (int p = 0; p < 2; p++)
                ldsm4(bfr[p], sB[s] + (wn * 32 + p * 16 + srow) * 128 + swz);
            #pragma unroll
            for (int mt = 0; mt < 4; mt++) {
                uint32_t af[4];
                ldsm4(af, sA[s] + (wm * 64 + mt * 16 + srow) * 128 + swz);
                mma16816(acc[mt][0], af, bfr[0][0], bfr[0][2]);
                mma16816(acc[mt][1], af, bfr[0][1], bfr[0][3]);
                mma16816(acc[mt][2], af, bfr[1][0], bfr[1][2]);
                mma16816(acc[mt][3], af, bfr[1][1], bfr[1][3]);
            }
        }
        __syncthreads();
        if (kt + 2 < GNCH)
            g_load(A, B, sA[s], sB[s], m0, n0, kt + 2, tid);
    }

    if (mode == 0) {
        #pragma unroll
        for (int mt = 0; mt < 4; mt++) {
            const int r0 = m0 + wm * 64 + mt * 16 + g;
            #pragma unroll
            for (int nt = 0; nt < 4; nt++) {
                const int col = n0 + wn * 32 + nt * 8 + tg * 2;
                float2 v0 = { acc[mt][nt][0], acc[mt][nt][1] };
                float2 v1 = { acc[mt][nt][2], acc[mt][nt][3] };
                *(float2*)(C + (size_t)r0 * ldc + col) = v0;
                *(float2*)(C + (size_t)(r0 + 8) * ldc + col) = v1;
            }
        }
    } else {
        const int sect = n0 >> 10;   // 0=q, 1=k, 2=v
        __nv_bfloat16* bh = (sect == 0) ? g_qh : (sect == 1) ? g_kh : g_vh;
        __nv_bfloat16* bl = (sect == 0) ? g_ql : (sect == 1) ? g_kl : g_vl;
        const float scl = (sect == 0) ? 0.125f : 1.0f;
        #pragma unroll
        for (int mt = 0; mt < 4; mt++) {
            const int r0 = m0 + wm * 64 + mt * 16 + g;
            #pragma unroll
            for (int nt = 0; nt < 4; nt++) {
                const int col = (n0 + wn * 32 + nt * 8 + tg * 2) & 1023;
                uint32_t lo0, lo1;
                uint32_t h0 = pack_hilo(acc[mt][nt][0] * scl, acc[mt][nt][1] * scl, lo0);
                uint32_t h1 = pack_hilo(acc[mt][nt][2] * scl, acc[mt][nt][3] * scl, lo1);
                *(uint32_t*)(bh + (size_t)r0 * DD + col) = h0;
                *(uint32_t*)(bl + (size_t)r0 * DD + col) = lo0;
                *(uint32_t*)(bh + (size_t)(r0 + 8) * DD + col) = h1;
                *(uint32_t*)(bl + (size_t)(r0 + 8) * DD + col) = lo1;
            }
        }
    }
}

// ---------------------------------------------------------------------------
// Flash attention, mma.sync. 8 warps, 128 q rows/CTA, 64-row KV tiles,
// double-buffered KV (cp.async 2-stage), per-warp causal skip.
// smem: qh[16KB] ql[16KB] | stage0: kh,kl,vh,vl (8KB each) | stage1: same.
// scores = qh.kh + ql.kh + qh.kl ; PV = ph.vh + pl.vh + ph.vl
// ---------------------------------------------------------------------------
#define SQ_BYTES 16384        // 128 rows x 128B
#define KVSTAGE 32768         // 4 planes x 8KB
#define ATTN_SMEM (2 * SQ_BYTES + 2 * KVSTAGE)   // 98304

__device__ __forceinline__ void kv_load(uint32_t kvbase, int b, int h,
                                        int kt, int tid)
{
    const int pl = tid >> 6;        // 0..3
    const int r = tid & 63;
    const __nv_bfloat16* gp = (pl == 0) ? g_kh : (pl == 1) ? g_kl
                             : (pl == 2) ? g_vh : g_vl;
    const __nv_bfloat16* src = gp + (size_t)(b * SS + kt * 64 + r) * DD + h * 64;
    const uint32_t d = kvbase + pl * 8192 + r * 128;
    const uint32_t swr = (uint32_t)((r & 7) << 4);
    #pragma unroll
    for (int i = 0; i < 8; i++)
        cp16(d + ((uint32_t)(i * 16) ^ swr), src + i * 8);
    cp_commit();
}

__global__ __launch_bounds__(256) void attn_mma()
{
    extern __shared__ char smem[];
    const uint32_t sb = smem_u32(smem);
    const uint32_t sQH = sb;
    const uint32_t sQL = sb + SQ_BYTES;
    const uint32_t sKV0 = sb + 2 * SQ_BYTES;

    const int tid = threadIdx.x;
    const int lane = tid & 31;
    const int w = tid >> 5;
    const int qt = (int)gridDim.x - 1 - (int)blockIdx.x;   // heavy CTAs first
    const int bh = blockIdx.y;
    const int b = bh >> 4;
    const int h = bh & 15;
    const int qbase = qt * 128;

    const float slope = exp2f(-0.5f * (float)(h + 1));
    const int g  = lane >> 2;
    const int tg = lane & 3;
    const int srow = (lane & 7) + ((lane >> 3) & 1) * 8;
    const uint32_t swz_row = (uint32_t)((lane & 7) << 4);

    const int qr0 = qbase + w * 16 + g;
    const int qr1 = qr0 + 8;
    const float fq0 = (float)qr0;
    const float fq1 = (float)qr1;
    const int wq_hi = qbase + w * 16 + 15;   // warp's max q row

    // ---- load q planes (128 rows x 2 planes), one row per thread
    {
        const int p = tid >> 7;
        const int r = tid & 127;
        const __nv_bfloat16* src =
            (p ? g_ql : g_qh) + (size_t)(b * SS + qbase + r) * DD + h * 64;
        const uint32_t d = (p ? sQL : sQH) + r * 128;
        const uint32_t swr = (uint32_t)((r & 7) << 4);
        #pragma unroll
        for (int i = 0; i < 8; i++)
            cp16(d + ((uint32_t)(i * 16) ^ swr), src + i * 8);
    }
    cp_commit();

    const int last = 2 * qt + 1;
    kv_load(sKV0, b, h, 0, tid);     // prologue: stage 0 = kt 0

    cp_wait<1>();                     // q planes ready
    __syncthreads();

    uint32_t qf[2][4][4];
    #pragma unroll
    for (int p = 0; p < 2; p++)
        #pragma unroll
        for (int kk = 0; kk < 4; kk++)
            ldsm4(qf[p][kk], (p ? sQL : sQH) + (w * 16 + srow) * 128 +
                  ((uint32_t)(kk * 32 + ((lane >> 4) << 4)) ^ swz_row));

    float acc[8][4];
    #pragma unroll
    for (int i = 0; i < 8; i++)
        #pragma unroll
        for (int j = 0; j < 4; j++) acc[i][j] = 0.f;
    float rm0 = -1e30f, rm1 = -1e30f, l0 = 0.f, l1 = 0.f;

    #pragma unroll 1
    for (int kt = 0; kt <= last; kt++) {
        const int s = kt & 1;
        const uint32_t kv = sKV0 + s * KVSTAGE;
        if (kt < last) { kv_load(sKV0 + (1 - s) * KVSTAGE, b, h, kt + 1, tid); cp_wait<1>(); }
        else cp_wait<0>();
        __syncthreads();

        if (kt * 64 <= wq_hi) {     // warp-uniform causal skip
            // ---- scores
            float S[8][4];
            #pragma unroll
            for (int i = 0; i < 8; i++)
                #pragma unroll
                for (int j = 0; j < 4; j++) S[i][j] = 0.f;

            #pragma unroll
            for (int kk = 0; kk < 4; kk++) {   // kh: qh & ql
                const uint32_t swz = (uint32_t)(kk * 32 + ((lane >> 4) << 4)) ^ swz_row;
                #pragma unroll
                for (int j = 0; j < 4; j++) {
                    uint32_t bf[4];
                    ldsm4(bf, kv + (j * 16 + srow) * 128 + swz);
                    mma16816(S[2 * j],     qf[0][kk], bf[0], bf[2]);
                    mma16816(S[2 * j + 1], qf[0][kk], bf[1], bf[3]);
                    mma16816(S[2 * j],     qf[1][kk], bf[0], bf[2]);
                    mma16816(S[2 * j + 1], qf[1][kk], bf[1], bf[3]);
                }
            }
            #pragma unroll
            for (int kk = 0; kk < 4; kk++) {   // kl: qh only
                const uint32_t swz = (uint32_t)(kk * 32 + ((lane >> 4) << 4)) ^ swz_row;
                #pragma unroll
                for (int j = 0; j < 4; j++) {
                    uint32_t bf[4];
                    ldsm4(bf, kv + 8192 + (j * 16 + srow) * 128 + swz);
                    mma16816(S[2 * j],     qf[0][kk], bf[0], bf[2]);
                    mma16816(S[2 * j + 1], qf[0][kk], bf[1], bf[3]);
                }
            }

            // ---- bias + causal mask + online softmax
            const float kb = (float)(kt * 64);
            const bool needmask = (kt * 64 + 63 > qbase + w * 16);
            float tm0 = -1e30f, tm1 = -1e30f;
            #pragma unroll
            for (int nt = 0; nt < 8; nt++) {
                const float c0 = kb + (float)(nt * 8 + tg * 2);
                const float c1 = c0 + 1.f;
                float s00 = S[nt][0] + slope * (fq0 - c0);
                float s01 = S[nt][1] + slope * (fq0 - c1);
                float s10 = S[nt][2] + slope * (fq1 - c0);
                float s11 = S[nt][3] + slope * (fq1 - c1);
                if (needmask) {
                    s00 = (c0 <= fq0) ? s00 : -1e30f;
                    s01 = (c1 <= fq0) ? s01 : -1e30f;
                    s10 = (c0 <= fq1) ? s10 : -1e30f;
                    s11 = (c1 <= fq1) ? s11 : -1e30f;
                }
                S[nt][0] = s00; S[nt][1] = s01; S[nt][2] = s10; S[nt][3] = s11;
                tm0 = fmaxf(tm0, fmaxf(s00, s01));
                tm1 = fmaxf(tm1, fmaxf(s10, s11));
            }
            tm0 = fmaxf(tm0, __shfl_xor_sync(0xffffffffu, tm0, 1));
            tm0 = fmaxf(tm0, __shfl_xor_sync(0xffffffffu, tm0, 2));
            tm1 = fmaxf(tm1, __shfl_xor_sync(0xffffffffu, tm1, 1));
            tm1 = fmaxf(tm1, __shfl_xor_sync(0xffffffffu, tm1, 2));

            const float nm0 = fmaxf(rm0, tm0);
            const float nm1 = fmaxf(rm1, tm1);
            const float corr0 = __expf(rm0 - nm0);
            const float corr1 = __expf(rm1 - nm1);
            rm0 = nm0; rm1 = nm1;

            float ts0 = 0.f, ts1 = 0.f;
            #pragma unroll
            for (int nt = 0; nt < 8; nt++) {
                S[nt][0] = __expf(S[nt][0] - rm0);
                S[nt][1] = __expf(S[nt][1] - rm0);
                S[nt][2] = __expf(S[nt][2] - rm1);
                S[nt][3] = __expf(S[nt][3] - rm1);
                ts0 += S[nt][0] + S[nt][1];
                ts1 += S[nt][2] + S[nt][3];
            }
            ts0 += __shfl_xor_sync(0xffffffffu, ts0, 1);
            ts0 += __shfl_xor_sync(0xffffffffu, ts0, 2);
            ts1 += __shfl_xor_sync(0xffffffffu, ts1, 1);
            ts1 += __shfl_xor_sync(0xffffffffu, ts1, 2);
            l0 = l0 * corr0 + ts0;
            l1 = l1 * corr1 + ts1;

            #pragma unroll
            for (int nt = 0; nt < 8; nt++) {
                acc[nt][0] *= corr0; acc[nt][1] *= corr0;
                acc[nt][2] *= corr1; acc[nt][3] *= corr1;
            }

            // ---- PV
            uint32_t ahs[4][4];
            #pragma unroll
            for (int kk = 0; kk < 4; kk++) {
                uint32_t al[4];
                ahs[kk][0] = pack_hilo(S[2 * kk][0],     S[2 * kk][1],     al[0]);
                ahs[kk][1] = pack_hilo(S[2 * kk][2],     S[2 * kk][3],     al[1]);
                ahs[kk][2] = pack_hilo(S[2 * kk + 1][0], S[2 * kk + 1][1], al[2]);
                ahs[kk][3] = pack_hilo(S[2 * kk + 1][2], S[2 * kk + 1][3], al[3]);
                const int vr = kk * 16 + ((lane >> 4) & 1) * 8 + (lane & 7);
                const uint32_t vb = (uint32_t)((((lane >> 3) & 1)) << 4);
                #pragma unroll
                for (int j = 0; j < 4; j++) {
                    uint32_t vf[4];
                    ldsm4t(vf, kv + 16384 + vr * 128 +
                           (((uint32_t)(j * 32) + vb) ^ ((uint32_t)(vr & 7) << 4)));
                    mma16816(acc[2 * j],     ahs[kk], vf[0], vf[2]);
                    mma16816(acc[2 * j + 1], ahs[kk], vf[1], vf[3]);
                    mma16816(acc[2 * j],     al,      vf[0], vf[2]);
                    mma16816(acc[2 * j + 1], al,      vf[1], vf[3]);
                }
            }
            #pragma unroll
            for (int kk = 0; kk < 4; kk++) {   // vl: ph only
                const int vr = kk * 16 + ((lane >> 4) & 1) * 8 + (lane & 7);
                const uint32_t vb = (uint32_t)((((lane >> 3) & 1)) << 4);
                #pragma unroll
                for (int j = 0; j < 4; j++) {
                    uint32_t vf[4];
                    ldsm4t(vf, kv + 24576 + vr * 128 +
                           (((uint32_t)(j * 32) + vb) ^ ((uint32_t)(vr & 7) << 4)));
                    mma16816(acc[2 * j],     ahs[kk], vf[0], vf[2]);
                    mma16816(acc[2 * j + 1], ahs[kk], vf[1], vf[3]);
                }
            }
        }
        __syncthreads();   // all reads of stage s done before it is refilled
    }

    // ---- epilogue: normalize, write 3-plane bf16 split ctx rows
    const float inv0 = 1.f / l0;
    const float inv1 = 1.f / l1;
    __nv_bfloat16* row0 = g_ctxc + (size_t)(b * SS + qr0) * GK3;
    __nv_bfloat16* row1 = g_ctxc + (size_t)(b * SS + qr1) * GK3;
    #pragma unroll
    for (int nt = 0; nt < 8; nt++) {
        const int c = h * 64 + nt * 8 + tg * 2;
        write_split3(row0, c, acc[nt][0] * inv0, acc[nt][1] * inv0);
        write_split3(row1, c, acc[nt][2] * inv1, acc[nt][3] * inv1);
    }
}

// ---------------------------------------------------------------------------
extern "C" void kernel_launch(void* const* d_in, const int* in_sizes, int n_in,
                              void* d_out, int out_size)
{
    (void)in_sizes; (void)n_in; (void)out_size;
    const float* x  = (const float*)d_in[0];
    const float* Wq = (const float*)d_in[1];
    const float* Wk = (const float*)d_in[2];
    const float* Wv = (const float*)d_in[3];
    const float* Wo = (const float*)d_in[4];
    float* out = (float*)d_out;

    __nv_bfloat16 *xc, *wc, *woc, *ctxc;
    cudaGetSymbolAddress((void**)&xc, g_xc);
    cudaGetSymbolAddress((void**)&wc, g_wc);
    cudaGetSymbolAddress((void**)&woc, g_woc);
    cudaGetSymbolAddress((void**)&ctxc, g_ctxc);

    const int SMEM_GEMM = 4 * GTILE;      // 65536
    static bool attr_set = false;
    if (!attr_set) {
        cudaFuncSetAttribute(gemm_mma, cudaFuncAttributeMaxDynamicSharedMemorySize, SMEM_GEMM);
        cudaFuncSetAttribute(attn_mma, cudaFuncAttributeMaxDynamicSharedMemorySize, ATTN_SMEM);
        attr_set = true;
    }

    // fp32 -> bf16 3-plane splits
    split3<<<(NTOK * DD + 255) / 256, 256>>>(x, xc, 0, NTOK * DD);
    split3_weights<<<dim3(DD * DD / 256, 4), 256>>>(Wq, Wk, Wv, Wo);

    // fused QKV projection with hi/lo epilogue
    gemm_mma<<<dim3(3 * DD / 128, NTOK / 128), 256, SMEM_GEMM>>>(xc, wc, nullptr, 0, 1);

    // attention (writes g_ctxc split directly)
    attn_mma<<<dim3(SS / 128, BB * HH), 256, ATTN_SMEM>>>();

    // output projection
    gemm_mma<<<dim3(DD / 128, NTOK / 128), 256, SMEM_GEMM>>>(ctxc, woc, out, DD, 0);
}